// round 8
// baseline (speedup 1.0000x reference)
#include <cuda_runtime.h>
#include <cuda_bf16.h>
#include <cstdint>

// Problem constants
#define BATCH 2
#define SEQ   2048
#define DIM   1024
#define HEADS 16
#define HD    64
#define MROWS (BATCH*SEQ)      // 4096
#define NQKV  (3*DIM)          // 3072

// Scratch (device globals: allocation-free)
__device__ float g_q[BATCH*HEADS*SEQ*HD];     // [b,h,s,d]
__device__ float g_k[BATCH*HEADS*SEQ*HD];
__device__ float g_v[BATCH*HEADS*SEQ*HD];
__device__ float g_attn[BATCH*SEQ*DIM];       // [b,s,h*64+d] (tf32-rounded)
__device__ float g_xr[MROWS*DIM];             // x rounded to tf32
__device__ float g_wqkvr[NQKV*DIM];           // w_qkv rounded to tf32
__device__ float g_wprojr[DIM*DIM];           // w_proj rounded to tf32

// ---------------------------------------------------------------------------
// helpers
// ---------------------------------------------------------------------------
__device__ __forceinline__ uint32_t f2tf32(float f) {
    uint32_t u;
    asm("cvt.rna.tf32.f32 %0, %1;" : "=r"(u) : "f"(f));
    return u;
}
__device__ __forceinline__ float ftf32(float f) { return __uint_as_float(f2tf32(f)); }

__device__ __forceinline__ float ex2(float x) {
    float r;
    asm("ex2.approx.f32 %0, %1;" : "=f"(r) : "f"(x));
    return r;
}

__device__ __forceinline__ void mma_tf32(float c[4], const uint32_t a[4], const uint32_t b[2]) {
    asm volatile(
        "mma.sync.aligned.m16n8k8.row.col.f32.tf32.tf32.f32 "
        "{%0,%1,%2,%3},{%4,%5,%6,%7},{%8,%9},{%0,%1,%2,%3};\n"
        : "+f"(c[0]), "+f"(c[1]), "+f"(c[2]), "+f"(c[3])
        : "r"(a[0]), "r"(a[1]), "r"(a[2]), "r"(a[3]), "r"(b[0]), "r"(b[1]));
}

// ---------------------------------------------------------------------------
// Elementwise tf32 rounding pre-pass (RNA). n must be divisible by 4.
// ---------------------------------------------------------------------------
__global__ __launch_bounds__(256)
void round_tf32_kernel(const float* __restrict__ in, float* __restrict__ out, int n4)
{
    int i = blockIdx.x * 256 + threadIdx.x;
    if (i < n4) {
        float4 v = ((const float4*)in)[i];
        ((float4*)out)[i] = make_float4(ftf32(v.x), ftf32(v.y), ftf32(v.z), ftf32(v.w));
    }
}

// ---------------------------------------------------------------------------
// TF32 GEMM: C[m,n] = sum_k A[m,k]*W[n,k] + bias[n]
// A, W must already be tf32-rounded. No cvt in the mainloop.
// BM=BN=128, BK=32, 256 threads, cp.async 3-stage, 1 barrier/iter,
// warp tile 32x64.
// ---------------------------------------------------------------------------
#define PK 36
#define GEMM_SMEM (3*2*128*PK*4)   // 110592 bytes

template<int SCATTER>
__global__ __launch_bounds__(256)
void gemm_tf32(const float* __restrict__ A,
               const float* __restrict__ W,
               const float* __restrict__ bias,
               float* __restrict__ out)
{
    extern __shared__ float sm[];
    float* As = sm;               // [3][128][PK]
    float* Bs = sm + 3*128*PK;    // [3][128][PK]

    const int tid  = threadIdx.x;
    const int wid  = tid >> 5;
    const int lane = tid & 31;
    const int m0 = blockIdx.y * 128;
    const int n0 = blockIdx.x * 128;
    const int wm = (wid & 3) * 32;
    const int wn = (wid >> 2) * 64;
    const int tg = lane >> 2;     // 0..7
    const int tk = lane & 3;      // 0..3

    float acc[2][8][4];
#pragma unroll
    for (int mt = 0; mt < 2; ++mt)
#pragma unroll
        for (int nt = 0; nt < 8; ++nt)
#pragma unroll
            for (int c = 0; c < 4; ++c) acc[mt][nt][c] = 0.f;

    const int K = 1024;
    const int NS = K / 32;

    auto stage = [&](int s, int buf) {
        const int k0 = s * 32;
#pragma unroll
        for (int i = 0; i < 4; ++i) {
            const int t   = tid + i * 256;   // 0..1023
            const int row = t >> 3;          // 0..127
            const int kc  = (t & 7) << 2;    // 0..28
            uint32_t sa = (uint32_t)__cvta_generic_to_shared(
                &As[buf*128*PK + row*PK + kc]);
            const float* ga = &A[(long)(m0 + row) * K + k0 + kc];
            asm volatile("cp.async.cg.shared.global [%0], [%1], 16;\n"
                         :: "r"(sa), "l"(ga));
            uint32_t sb = (uint32_t)__cvta_generic_to_shared(
                &Bs[buf*128*PK + row*PK + kc]);
            const float* gb = &W[(long)(n0 + row) * K + k0 + kc];
            asm volatile("cp.async.cg.shared.global [%0], [%1], 16;\n"
                         :: "r"(sb), "l"(gb));
        }
        asm volatile("cp.async.commit_group;\n");
    };

    stage(0, 0);
    stage(1, 1);

    int buf = 0;
    for (int s = 0; s < NS; ++s) {
        if (s + 1 < NS) {
            asm volatile("cp.async.wait_group 1;\n");
        } else {
            asm volatile("cp.async.wait_group 0;\n");
        }
        __syncthreads();
        if (s + 2 < NS) {
            int nb = buf + 2; if (nb >= 3) nb -= 3;
            stage(s + 2, nb);
        }

        const float* as = &As[buf*128*PK];
        const float* bs = &Bs[buf*128*PK];
#pragma unroll
        for (int k8 = 0; k8 < 32; k8 += 8) {
            uint32_t af[2][4], bf[8][2];
#pragma unroll
            for (int mt = 0; mt < 2; ++mt) {
                const float* p = &as[(wm + mt*16 + tg)*PK + k8 + tk];
                af[mt][0] = __float_as_uint(p[0]);
                af[mt][1] = __float_as_uint(p[8*PK]);
                af[mt][2] = __float_as_uint(p[4]);
                af[mt][3] = __float_as_uint(p[8*PK + 4]);
            }
#pragma unroll
            for (int nt = 0; nt < 8; ++nt) {
                const float* p = &bs[(wn + nt*8 + tg)*PK + k8 + tk];
                bf[nt][0] = __float_as_uint(p[0]);
                bf[nt][1] = __float_as_uint(p[4]);
            }
#pragma unroll
            for (int mt = 0; mt < 2; ++mt)
#pragma unroll
                for (int nt = 0; nt < 8; ++nt)
                    mma_tf32(acc[mt][nt], af[mt], bf[nt]);
        }
        if (++buf == 3) buf = 0;
    }

    // epilogue
#pragma unroll
    for (int mt = 0; mt < 2; ++mt) {
#pragma unroll
        for (int nt = 0; nt < 8; ++nt) {
#pragma unroll
            for (int c = 0; c < 4; ++c) {
                const int m = m0 + wm + mt*16 + tg + ((c >= 2) ? 8 : 0);
                const int n = n0 + wn + nt*8 + 2*tk + (c & 1);
                const float v = acc[mt][nt][c] + bias[n];
                if (SCATTER) {
                    const int b = m >> 11, sq = m & 2047;
                    const int part = n >> 10, h = (n >> 6) & 15, d = n & 63;
                    float* dst = (part == 0) ? g_q : (part == 1) ? g_k : g_v;
                    dst[((((long)b*HEADS + h)*SEQ) + sq)*HD + d] = ftf32(v);
                } else {
                    out[(long)m * 1024 + n] = v;
                }
            }
        }
    }
}

// ---------------------------------------------------------------------------
// Flash attention v4: register-resident, base-2 softmax, 1 barrier/iter.
// BQ=128, BKV=64, 256 threads = 8 warps; each warp owns 16 rows.
// Q fragments in registers, pre-scaled by 0.125*log2(e).
// ---------------------------------------------------------------------------
#define KP3 68
#define VP3 72
#define PP3 68
#define F3_KOFF 0
#define F3_VOFF (2*64*KP3)
#define F3_POFF (F3_VOFF + 2*64*VP3)
#define F3_SMEM ((F3_POFF + 8*16*PP3)*4)   // 106496 bytes

__global__ __launch_bounds__(256, 2)
void flash4(float* __restrict__ Ob)
{
    extern __shared__ float sm[];
    float* Ksm = sm + F3_KOFF;   // [2][64][KP3]
    float* Vsm = sm + F3_VOFF;   // [2][64][VP3]
    float* Psm = sm + F3_POFF;   // [8 warps][16][PP3]

    const int tid  = threadIdx.x;
    const int wid  = tid >> 5;
    const int lane = tid & 31;
    const int tg = lane >> 2;    // 0..7
    const int tk = lane & 3;     // 0..3
    const int bh = blockIdx.y;
    const int q0 = blockIdx.x * 128;
    const int wm = wid * 16;

    const float* Qg = g_q + ((long)bh*SEQ + q0) * HD;
    const float* Kg = g_k + (long)bh*SEQ*HD;
    const float* Vg = g_v + (long)bh*SEQ*HD;
    float* Pw = Psm + wid*16*PP3;

    // Q fragments in registers, pre-scaled by 0.125*log2(e) (base-2 softmax)
    const float qs = 0.125f * 1.4426950408889634f;
    uint32_t qf[8][4];
#pragma unroll
    for (int i = 0; i < 8; ++i) {
        const int k = i * 8;
        qf[i][0] = f2tf32(Qg[(wm+tg)*HD   + k+tk]   * qs);
        qf[i][1] = f2tf32(Qg[(wm+tg+8)*HD + k+tk]   * qs);
        qf[i][2] = f2tf32(Qg[(wm+tg)*HD   + k+tk+4] * qs);
        qf[i][3] = f2tf32(Qg[(wm+tg+8)*HD + k+tk+4] * qs);
    }

    float oacc[8][4];
#pragma unroll
    for (int nt = 0; nt < 8; ++nt)
#pragma unroll
        for (int c = 0; c < 4; ++c) oacc[nt][c] = 0.f;
    float m0 = -1e30f, m1 = -1e30f, l0 = 0.f, l1 = 0.f;

    auto stage = [&](int s, int b2) {
        const float* Kt = Kg + (long)s*64*HD;
        const float* Vt = Vg + (long)s*64*HD;
#pragma unroll
        for (int i = 0; i < 4; ++i) {
            const int t = tid + i*256;       // 0..1023
            const int r = t >> 4;            // 0..63
            const int c = (t & 15) << 2;     // 0..60
            uint32_t dk = (uint32_t)__cvta_generic_to_shared(
                &Ksm[b2*64*KP3 + r*KP3 + c]);
            asm volatile("cp.async.cg.shared.global [%0], [%1], 16;\n"
                         :: "r"(dk), "l"(&Kt[r*HD + c]));
            uint32_t dv = (uint32_t)__cvta_generic_to_shared(
                &Vsm[b2*64*VP3 + r*VP3 + c]);
            asm volatile("cp.async.cg.shared.global [%0], [%1], 16;\n"
                         :: "r"(dv), "l"(&Vt[r*HD + c]));
        }
        asm volatile("cp.async.commit_group;\n");
    };

    stage(0, 0);

    const int NT = SEQ / 64;   // 32
    for (int kt = 0; kt < NT; ++kt) {
        const int buf = kt & 1;
        asm volatile("cp.async.wait_group 0;\n");
        __syncthreads();   // stage(kt) visible; compute(kt-1) done with buf^1
        if (kt + 1 < NT) stage(kt + 1, buf ^ 1);

        const float* Kb = &Ksm[buf*64*KP3];
        const float* Vb = &Vsm[buf*64*VP3];

        // ---- S2 = (Q*qs) K^T : 16x64 per warp, in registers ----
        float sacc[8][4];
#pragma unroll
        for (int nt = 0; nt < 8; ++nt)
#pragma unroll
            for (int c = 0; c < 4; ++c) sacc[nt][c] = 0.f;
#pragma unroll
        for (int i = 0; i < 8; ++i) {
            const int k8 = i * 8;
            uint32_t bf[8][2];
#pragma unroll
            for (int nt = 0; nt < 8; ++nt) {
                const float* p = &Kb[(nt*8 + tg)*KP3 + k8 + tk];
                bf[nt][0] = __float_as_uint(p[0]);
                bf[nt][1] = __float_as_uint(p[4]);
            }
#pragma unroll
            for (int nt = 0; nt < 8; ++nt)
                mma_tf32(sacc[nt], qf[i], bf[nt]);
        }

        // ---- online softmax (base 2), fully in registers ----
        float r0 = -1e30f, r1 = -1e30f;
#pragma unroll
        for (int nt = 0; nt < 8; ++nt) {
            r0 = fmaxf(r0, fmaxf(sacc[nt][0], sacc[nt][1]));
            r1 = fmaxf(r1, fmaxf(sacc[nt][2], sacc[nt][3]));
        }
        r0 = fmaxf(r0, __shfl_xor_sync(0xffffffffu, r0, 1));
        r0 = fmaxf(r0, __shfl_xor_sync(0xffffffffu, r0, 2));
        r1 = fmaxf(r1, __shfl_xor_sync(0xffffffffu, r1, 1));
        r1 = fmaxf(r1, __shfl_xor_sync(0xffffffffu, r1, 2));
        const float mn0 = fmaxf(m0, r0);
        const float mn1 = fmaxf(m1, r1);
        const float a0 = ex2(m0 - mn0);
        const float a1 = ex2(m1 - mn1);
        float s0 = 0.f, s1 = 0.f;
#pragma unroll
        for (int nt = 0; nt < 8; ++nt) {
            float p0 = ftf32(ex2(sacc[nt][0] - mn0));
            float p1 = ftf32(ex2(sacc[nt][1] - mn0));
            float p2 = ftf32(ex2(sacc[nt][2] - mn1));
            float p3 = ftf32(ex2(sacc[nt][3] - mn1));
            sacc[nt][0] = p0; sacc[nt][1] = p1;
            sacc[nt][2] = p2; sacc[nt][3] = p3;
            s0 += p0 + p1;
            s1 += p2 + p3;
        }
        s0 += __shfl_xor_sync(0xffffffffu, s0, 1);
        s0 += __shfl_xor_sync(0xffffffffu, s0, 2);
        s1 += __shfl_xor_sync(0xffffffffu, s1, 1);
        s1 += __shfl_xor_sync(0xffffffffu, s1, 2);
        l0 = l0 * a0 + s0;
        l1 = l1 * a1 + s1;
        m0 = mn0; m1 = mn1;
#pragma unroll
        for (int nt = 0; nt < 8; ++nt) {
            oacc[nt][0] *= a0; oacc[nt][1] *= a0;
            oacc[nt][2] *= a1; oacc[nt][3] *= a1;
        }

        // ---- P to per-warp smem (C-frag -> A-frag layout fix) ----
#pragma unroll
        for (int nt = 0; nt < 8; ++nt) {
            *(float2*)&Pw[tg*PP3     + nt*8 + 2*tk] = make_float2(sacc[nt][0], sacc[nt][1]);
            *(float2*)&Pw[(tg+8)*PP3 + nt*8 + 2*tk] = make_float2(sacc[nt][2], sacc[nt][3]);
        }
        __syncwarp();

        // ---- O += P @ V ----
#pragma unroll
        for (int i = 0; i < 8; ++i) {
            const int k8 = i * 8;
            uint32_t af[4];
            af[0] = __float_as_uint(Pw[tg*PP3     + k8 + tk]);
            af[1] = __float_as_uint(Pw[(tg+8)*PP3 + k8 + tk]);
            af[2] = __float_as_uint(Pw[tg*PP3     + k8 + tk + 4]);
            af[3] = __float_as_uint(Pw[(tg+8)*PP3 + k8 + tk + 4]);
            uint32_t bf[8][2];
#pragma unroll
            for (int nt = 0; nt < 8; ++nt) {
                bf[nt][0] = __float_as_uint(Vb[(k8+tk)*VP3   + nt*8 + tg]);
                bf[nt][1] = __float_as_uint(Vb[(k8+tk+4)*VP3 + nt*8 + tg]);
            }
#pragma unroll
            for (int nt = 0; nt < 8; ++nt)
                mma_tf32(oacc[nt], af, bf[nt]);
        }
    }

    // ---- finalize + store (tf32-rounded) to [B,S,D] ----
    const int b = bh >> 4, h = bh & 15;
    const float i0 = 1.f / l0;
    const float i1 = 1.f / l1;
    const long row0 = (long)b*SEQ + q0 + wm + tg;
    const long row1 = row0 + 8;
#pragma unroll
    for (int nt = 0; nt < 8; ++nt) {
        const int col = h*HD + nt*8 + 2*tk;
        *(float2*)&Ob[row0*DIM + col] =
            make_float2(ftf32(oacc[nt][0]*i0), ftf32(oacc[nt][1]*i0));
        *(float2*)&Ob[row1*DIM + col] =
            make_float2(ftf32(oacc[nt][2]*i1), ftf32(oacc[nt][3]*i1));
    }
}

// ---------------------------------------------------------------------------
extern "C" void kernel_launch(void* const* d_in, const int* in_sizes, int n_in,
                              void* d_out, int out_size)
{
    const float* x      = (const float*)d_in[0];
    const float* w_qkv  = (const float*)d_in[1];
    const float* b_qkv  = (const float*)d_in[2];
    const float* w_proj = (const float*)d_in[3];
    const float* b_proj = (const float*)d_in[4];
    float* out = (float*)d_out;

    float *attn_ptr = nullptr, *xr = nullptr, *wqkvr = nullptr, *wprojr = nullptr;
    cudaGetSymbolAddress((void**)&attn_ptr, g_attn);
    cudaGetSymbolAddress((void**)&xr, g_xr);
    cudaGetSymbolAddress((void**)&wqkvr, g_wqkvr);
    cudaGetSymbolAddress((void**)&wprojr, g_wprojr);

    static bool attr_done = false;
    if (!attr_done) {
        cudaFuncSetAttribute(gemm_tf32<1>,
            cudaFuncAttributeMaxDynamicSharedMemorySize, GEMM_SMEM);
        cudaFuncSetAttribute(gemm_tf32<0>,
            cudaFuncAttributeMaxDynamicSharedMemorySize, GEMM_SMEM);
        cudaFuncSetAttribute(flash4,
            cudaFuncAttributeMaxDynamicSharedMemorySize, F3_SMEM);
        attr_done = true;
    }

    // 0) tf32 rounding pre-pass (RNA) for GEMM operands
    {
        int n4x = MROWS*DIM/4, n4q = NQKV*DIM/4, n4p = DIM*DIM/4;
        round_tf32_kernel<<<(n4x+255)/256, 256>>>(x, xr, n4x);
        round_tf32_kernel<<<(n4q+255)/256, 256>>>(w_qkv, wqkvr, n4q);
        round_tf32_kernel<<<(n4p+255)/256, 256>>>(w_proj, wprojr, n4p);
    }
    // 1) QKV GEMM + bias -> scatter into Q/K/V [b,h,s,d] (tf32-rounded)
    {
        dim3 grid(NQKV/128, MROWS/128);   // (24, 32)
        gemm_tf32<1><<<grid, 256, GEMM_SMEM>>>(xr, wqkvr, b_qkv, nullptr);
    }
    // 2) flash attention v4 -> g_attn [b,s,D] (tf32-rounded)
    {
        dim3 grid(SEQ/128, BATCH*HEADS);  // (16, 32)
        flash4<<<grid, 256, F3_SMEM>>>(attn_ptr);
    }
    // 3) output projection + bias -> d_out
    {
        dim3 grid(DIM/128, MROWS/128);    // (8, 32)
        gemm_tf32<0><<<grid, 256, GEMM_SMEM>>>(attn_ptr, wprojr, b_proj, out);
    }
}

// round 13
// speedup vs baseline: 1.0750x; 1.0750x over previous
#include <cuda_runtime.h>
#include <cuda_bf16.h>
#include <cstdint>

// Problem constants
#define BATCH 2
#define SEQ   2048
#define DIM   1024
#define HEADS 16
#define HD    64
#define MROWS (BATCH*SEQ)      // 4096
#define NQKV  (3*DIM)          // 3072

// Scratch (device globals: allocation-free)
__device__ float g_q[BATCH*HEADS*SEQ*HD];     // [b,h,s,d]
__device__ float g_k[BATCH*HEADS*SEQ*HD];
__device__ float g_v[BATCH*HEADS*SEQ*HD];
__device__ float g_attn[BATCH*SEQ*DIM];       // [b,s,h*64+d] (tf32-rounded)
__device__ float g_xr[MROWS*DIM];             // x rounded to tf32
__device__ float g_wqkvr[NQKV*DIM];           // w_qkv rounded to tf32
__device__ float g_wprojr[DIM*DIM];           // w_proj rounded to tf32

// ---------------------------------------------------------------------------
// helpers
// ---------------------------------------------------------------------------
__device__ __forceinline__ uint32_t f2tf32(float f) {
    uint32_t u;
    asm("cvt.rna.tf32.f32 %0, %1;" : "=r"(u) : "f"(f));
    return u;
}
__device__ __forceinline__ float ftf32(float f) { return __uint_as_float(f2tf32(f)); }

__device__ __forceinline__ float ex2(float x) {
    float r;
    asm("ex2.approx.f32 %0, %1;" : "=f"(r) : "f"(x));
    return r;
}

__device__ __forceinline__ void mma_tf32(float c[4], const uint32_t a[4], const uint32_t b[2]) {
    asm volatile(
        "mma.sync.aligned.m16n8k8.row.col.f32.tf32.tf32.f32 "
        "{%0,%1,%2,%3},{%4,%5,%6,%7},{%8,%9},{%0,%1,%2,%3};\n"
        : "+f"(c[0]), "+f"(c[1]), "+f"(c[2]), "+f"(c[3])
        : "r"(a[0]), "r"(a[1]), "r"(a[2]), "r"(a[3]), "r"(b[0]), "r"(b[1]));
}

// ---------------------------------------------------------------------------
// Fused tf32 rounding pre-pass (RNA) for x, w_qkv, w_proj in ONE launch.
// Sizes in float4 units.
// ---------------------------------------------------------------------------
#define N4X (MROWS*DIM/4)     // 1048576
#define N4Q (NQKV*DIM/4)      // 786432
#define N4P (DIM*DIM/4)       // 262144
#define N4TOT (N4X + N4Q + N4P)

__global__ __launch_bounds__(256)
void round3_kernel(const float* __restrict__ x,  float* __restrict__ xo,
                   const float* __restrict__ wq, float* __restrict__ wqo,
                   const float* __restrict__ wp, float* __restrict__ wpo)
{
    int i = blockIdx.x * 256 + threadIdx.x;
    const float4* in; float4* out; int j;
    if (i < N4X)            { in = (const float4*)x;  out = (float4*)xo;  j = i; }
    else if (i < N4X + N4Q) { in = (const float4*)wq; out = (float4*)wqo; j = i - N4X; }
    else if (i < N4TOT)     { in = (const float4*)wp; out = (float4*)wpo; j = i - N4X - N4Q; }
    else return;
    float4 v = in[j];
    out[j] = make_float4(ftf32(v.x), ftf32(v.y), ftf32(v.z), ftf32(v.w));
}

// ---------------------------------------------------------------------------
// TF32 GEMM (R7 config — measured best): C[m,n] = sum_k A[m,k]*W[n,k] + bias[n]
// BM=BN=128, BK=32, 256 threads, cp.async 2-stage, warp tile 32x64.
// A, W must already be tf32-rounded. No cvt in the mainloop.
// ---------------------------------------------------------------------------
#define PK 36
#define GEMM_SMEM (2*2*128*PK*4)   // 73728 bytes

template<int SCATTER>
__global__ __launch_bounds__(256)
void gemm_tf32(const float* __restrict__ A,
               const float* __restrict__ W,
               const float* __restrict__ bias,
               float* __restrict__ out)
{
    extern __shared__ float sm[];
    float* As = sm;               // [2][128][PK]
    float* Bs = sm + 2*128*PK;    // [2][128][PK]

    const int tid  = threadIdx.x;
    const int wid  = tid >> 5;
    const int lane = tid & 31;
    const int m0 = blockIdx.y * 128;
    const int n0 = blockIdx.x * 128;
    const int wm = (wid & 3) * 32;
    const int wn = (wid >> 2) * 64;
    const int tg = lane >> 2;     // 0..7
    const int tk = lane & 3;      // 0..3

    float acc[2][8][4];
#pragma unroll
    for (int mt = 0; mt < 2; ++mt)
#pragma unroll
        for (int nt = 0; nt < 8; ++nt)
#pragma unroll
            for (int c = 0; c < 4; ++c) acc[mt][nt][c] = 0.f;

    const int K = 1024;
    const int NS = K / 32;

    auto stage = [&](int s, int buf) {
        const int k0 = s * 32;
#pragma unroll
        for (int i = 0; i < 4; ++i) {
            const int t   = tid + i * 256;   // 0..1023
            const int row = t >> 3;          // 0..127
            const int kc  = (t & 7) << 2;    // 0..28
            uint32_t sa = (uint32_t)__cvta_generic_to_shared(
                &As[buf*128*PK + row*PK + kc]);
            const float* ga = &A[(long)(m0 + row) * K + k0 + kc];
            asm volatile("cp.async.cg.shared.global [%0], [%1], 16;\n"
                         :: "r"(sa), "l"(ga));
            uint32_t sb = (uint32_t)__cvta_generic_to_shared(
                &Bs[buf*128*PK + row*PK + kc]);
            const float* gb = &W[(long)(n0 + row) * K + k0 + kc];
            asm volatile("cp.async.cg.shared.global [%0], [%1], 16;\n"
                         :: "r"(sb), "l"(gb));
        }
        asm volatile("cp.async.commit_group;\n");
    };

    stage(0, 0);

    for (int s = 0; s < NS; ++s) {
        const int buf = s & 1;
        if (s + 1 < NS) {
            stage(s + 1, buf ^ 1);
            asm volatile("cp.async.wait_group 1;\n");
        } else {
            asm volatile("cp.async.wait_group 0;\n");
        }
        __syncthreads();

        const float* as = &As[buf*128*PK];
        const float* bs = &Bs[buf*128*PK];
#pragma unroll
        for (int k8 = 0; k8 < 32; k8 += 8) {
            uint32_t af[2][4], bf[8][2];
#pragma unroll
            for (int mt = 0; mt < 2; ++mt) {
                const float* p = &as[(wm + mt*16 + tg)*PK + k8 + tk];
                af[mt][0] = __float_as_uint(p[0]);
                af[mt][1] = __float_as_uint(p[8*PK]);
                af[mt][2] = __float_as_uint(p[4]);
                af[mt][3] = __float_as_uint(p[8*PK + 4]);
            }
#pragma unroll
            for (int nt = 0; nt < 8; ++nt) {
                const float* p = &bs[(wn + nt*8 + tg)*PK + k8 + tk];
                bf[nt][0] = __float_as_uint(p[0]);
                bf[nt][1] = __float_as_uint(p[4]);
            }
#pragma unroll
            for (int mt = 0; mt < 2; ++mt)
#pragma unroll
                for (int nt = 0; nt < 8; ++nt)
                    mma_tf32(acc[mt][nt], af[mt], bf[nt]);
        }
        __syncthreads();
    }

    // epilogue (float2 stores: c pairs (0,1) and (2,3) are adjacent in n)
#pragma unroll
    for (int mt = 0; mt < 2; ++mt) {
#pragma unroll
        for (int nt = 0; nt < 8; ++nt) {
            const int n = n0 + wn + nt*8 + 2*tk;
#pragma unroll
            for (int half = 0; half < 2; ++half) {
                const int m = m0 + wm + mt*16 + tg + half*8;
                const float v0 = acc[mt][nt][half*2]     + bias[n];
                const float v1 = acc[mt][nt][half*2 + 1] + bias[n + 1];
                if (SCATTER) {
                    const int b = m >> 11, sq = m & 2047;
                    const int part = n >> 10, h = (n >> 6) & 15, d = n & 63;
                    float* dst = (part == 0) ? g_q : (part == 1) ? g_k : g_v;
                    *(float2*)&dst[((((long)b*HEADS + h)*SEQ) + sq)*HD + d] =
                        make_float2(ftf32(v0), ftf32(v1));
                } else {
                    *(float2*)&out[(long)m * 1024 + n] = make_float2(v0, v1);
                }
            }
        }
    }
}

// ---------------------------------------------------------------------------
// Flash attention v4: register-resident, base-2 softmax, 1 barrier/iter.
// BQ=128, BKV=64, 256 threads = 8 warps; each warp owns 16 rows.
// Q fragments in registers, pre-scaled by 0.125*log2(e).
// ---------------------------------------------------------------------------
#define KP3 68
#define VP3 72
#define PP3 68
#define F3_KOFF 0
#define F3_VOFF (2*64*KP3)
#define F3_POFF (F3_VOFF + 2*64*VP3)
#define F3_SMEM ((F3_POFF + 8*16*PP3)*4)   // 106496 bytes

__global__ __launch_bounds__(256, 2)
void flash4(float* __restrict__ Ob)
{
    extern __shared__ float sm[];
    float* Ksm = sm + F3_KOFF;   // [2][64][KP3]
    float* Vsm = sm + F3_VOFF;   // [2][64][VP3]
    float* Psm = sm + F3_POFF;   // [8 warps][16][PP3]

    const int tid  = threadIdx.x;
    const int wid  = tid >> 5;
    const int lane = tid & 31;
    const int tg = lane >> 2;    // 0..7
    const int tk = lane & 3;     // 0..3
    const int bh = blockIdx.y;
    const int q0 = blockIdx.x * 128;
    const int wm = wid * 16;

    const float* Qg = g_q + ((long)bh*SEQ + q0) * HD;
    const float* Kg = g_k + (long)bh*SEQ*HD;
    const float* Vg = g_v + (long)bh*SEQ*HD;
    float* Pw = Psm + wid*16*PP3;

    // Q fragments in registers, pre-scaled by 0.125*log2(e) (base-2 softmax)
    const float qs = 0.125f * 1.4426950408889634f;
    uint32_t qf[8][4];
#pragma unroll
    for (int i = 0; i < 8; ++i) {
        const int k = i * 8;
        qf[i][0] = f2tf32(Qg[(wm+tg)*HD   + k+tk]   * qs);
        qf[i][1] = f2tf32(Qg[(wm+tg+8)*HD + k+tk]   * qs);
        qf[i][2] = f2tf32(Qg[(wm+tg)*HD   + k+tk+4] * qs);
        qf[i][3] = f2tf32(Qg[(wm+tg+8)*HD + k+tk+4] * qs);
    }

    float oacc[8][4];
#pragma unroll
    for (int nt = 0; nt < 8; ++nt)
#pragma unroll
        for (int c = 0; c < 4; ++c) oacc[nt][c] = 0.f;
    float m0 = -1e30f, m1 = -1e30f, l0 = 0.f, l1 = 0.f;

    auto stage = [&](int s, int b2) {
        const float* Kt = Kg + (long)s*64*HD;
        const float* Vt = Vg + (long)s*64*HD;
#pragma unroll
        for (int i = 0; i < 4; ++i) {
            const int t = tid + i*256;       // 0..1023
            const int r = t >> 4;            // 0..63
            const int c = (t & 15) << 2;     // 0..60
            uint32_t dk = (uint32_t)__cvta_generic_to_shared(
                &Ksm[b2*64*KP3 + r*KP3 + c]);
            asm volatile("cp.async.cg.shared.global [%0], [%1], 16;\n"
                         :: "r"(dk), "l"(&Kt[r*HD + c]));
            uint32_t dv = (uint32_t)__cvta_generic_to_shared(
                &Vsm[b2*64*VP3 + r*VP3 + c]);
            asm volatile("cp.async.cg.shared.global [%0], [%1], 16;\n"
                         :: "r"(dv), "l"(&Vt[r*HD + c]));
        }
        asm volatile("cp.async.commit_group;\n");
    };

    stage(0, 0);

    const int NT = SEQ / 64;   // 32
    for (int kt = 0; kt < NT; ++kt) {
        const int buf = kt & 1;
        asm volatile("cp.async.wait_group 0;\n");
        __syncthreads();   // stage(kt) visible; compute(kt-1) done with buf^1
        if (kt + 1 < NT) stage(kt + 1, buf ^ 1);

        const float* Kb = &Ksm[buf*64*KP3];
        const float* Vb = &Vsm[buf*64*VP3];

        // ---- S2 = (Q*qs) K^T : 16x64 per warp, in registers ----
        float sacc[8][4];
#pragma unroll
        for (int nt = 0; nt < 8; ++nt)
#pragma unroll
            for (int c = 0; c < 4; ++c) sacc[nt][c] = 0.f;
#pragma unroll
        for (int i = 0; i < 8; ++i) {
            const int k8 = i * 8;
            uint32_t bf[8][2];
#pragma unroll
            for (int nt = 0; nt < 8; ++nt) {
                const float* p = &Kb[(nt*8 + tg)*KP3 + k8 + tk];
                bf[nt][0] = __float_as_uint(p[0]);
                bf[nt][1] = __float_as_uint(p[4]);
            }
#pragma unroll
            for (int nt = 0; nt < 8; ++nt)
                mma_tf32(sacc[nt], qf[i], bf[nt]);
        }

        // ---- online softmax (base 2), fully in registers ----
        float r0 = -1e30f, r1 = -1e30f;
#pragma unroll
        for (int nt = 0; nt < 8; ++nt) {
            r0 = fmaxf(r0, fmaxf(sacc[nt][0], sacc[nt][1]));
            r1 = fmaxf(r1, fmaxf(sacc[nt][2], sacc[nt][3]));
        }
        r0 = fmaxf(r0, __shfl_xor_sync(0xffffffffu, r0, 1));
        r0 = fmaxf(r0, __shfl_xor_sync(0xffffffffu, r0, 2));
        r1 = fmaxf(r1, __shfl_xor_sync(0xffffffffu, r1, 1));
        r1 = fmaxf(r1, __shfl_xor_sync(0xffffffffu, r1, 2));
        const float mn0 = fmaxf(m0, r0);
        const float mn1 = fmaxf(m1, r1);
        const float a0 = ex2(m0 - mn0);
        const float a1 = ex2(m1 - mn1);
        float s0 = 0.f, s1 = 0.f;
#pragma unroll
        for (int nt = 0; nt < 8; ++nt) {
            float p0 = ftf32(ex2(sacc[nt][0] - mn0));
            float p1 = ftf32(ex2(sacc[nt][1] - mn0));
            float p2 = ftf32(ex2(sacc[nt][2] - mn1));
            float p3 = ftf32(ex2(sacc[nt][3] - mn1));
            sacc[nt][0] = p0; sacc[nt][1] = p1;
            sacc[nt][2] = p2; sacc[nt][3] = p3;
            s0 += p0 + p1;
            s1 += p2 + p3;
        }
        s0 += __shfl_xor_sync(0xffffffffu, s0, 1);
        s0 += __shfl_xor_sync(0xffffffffu, s0, 2);
        s1 += __shfl_xor_sync(0xffffffffu, s1, 1);
        s1 += __shfl_xor_sync(0xffffffffu, s1, 2);
        l0 = l0 * a0 + s0;
        l1 = l1 * a1 + s1;
        m0 = mn0; m1 = mn1;
#pragma unroll
        for (int nt = 0; nt < 8; ++nt) {
            oacc[nt][0] *= a0; oacc[nt][1] *= a0;
            oacc[nt][2] *= a1; oacc[nt][3] *= a1;
        }

        // ---- P to per-warp smem (C-frag -> A-frag layout fix) ----
#pragma unroll
        for (int nt = 0; nt < 8; ++nt) {
            *(float2*)&Pw[tg*PP3     + nt*8 + 2*tk] = make_float2(sacc[nt][0], sacc[nt][1]);
            *(float2*)&Pw[(tg+8)*PP3 + nt*8 + 2*tk] = make_float2(sacc[nt][2], sacc[nt][3]);
        }
        __syncwarp();

        // ---- O += P @ V ----
#pragma unroll
        for (int i = 0; i < 8; ++i) {
            const int k8 = i * 8;
            uint32_t af[4];
            af[0] = __float_as_uint(Pw[tg*PP3     + k8 + tk]);
            af[1] = __float_as_uint(Pw[(tg+8)*PP3 + k8 + tk]);
            af[2] = __float_as_uint(Pw[tg*PP3     + k8 + tk + 4]);
            af[3] = __float_as_uint(Pw[(tg+8)*PP3 + k8 + tk + 4]);
            uint32_t bf[8][2];
#pragma unroll
            for (int nt = 0; nt < 8; ++nt) {
                bf[nt][0] = __float_as_uint(Vb[(k8+tk)*VP3   + nt*8 + tg]);
                bf[nt][1] = __float_as_uint(Vb[(k8+tk+4)*VP3 + nt*8 + tg]);
            }
#pragma unroll
            for (int nt = 0; nt < 8; ++nt)
                mma_tf32(oacc[nt], af, bf[nt]);
        }
    }

    // ---- finalize + store (tf32-rounded) to [B,S,D] ----
    const int b = bh >> 4, h = bh & 15;
    const float i0 = 1.f / l0;
    const float i1 = 1.f / l1;
    const long row0 = (long)b*SEQ + q0 + wm + tg;
    const long row1 = row0 + 8;
#pragma unroll
    for (int nt = 0; nt < 8; ++nt) {
        const int col = h*HD + nt*8 + 2*tk;
        *(float2*)&Ob[row0*DIM + col] =
            make_float2(ftf32(oacc[nt][0]*i0), ftf32(oacc[nt][1]*i0));
        *(float2*)&Ob[row1*DIM + col] =
            make_float2(ftf32(oacc[nt][2]*i1), ftf32(oacc[nt][3]*i1));
    }
}

// ---------------------------------------------------------------------------
extern "C" void kernel_launch(void* const* d_in, const int* in_sizes, int n_in,
                              void* d_out, int out_size)
{
    const float* x      = (const float*)d_in[0];
    const float* w_qkv  = (const float*)d_in[1];
    const float* b_qkv  = (const float*)d_in[2];
    const float* w_proj = (const float*)d_in[3];
    const float* b_proj = (const float*)d_in[4];
    float* out = (float*)d_out;

    float *attn_ptr = nullptr, *xr = nullptr, *wqkvr = nullptr, *wprojr = nullptr;
    cudaGetSymbolAddress((void**)&attn_ptr, g_attn);
    cudaGetSymbolAddress((void**)&xr, g_xr);
    cudaGetSymbolAddress((void**)&wqkvr, g_wqkvr);
    cudaGetSymbolAddress((void**)&wprojr, g_wprojr);

    cudaFuncSetAttribute(gemm_tf32<1>,
        cudaFuncAttributeMaxDynamicSharedMemorySize, GEMM_SMEM);
    cudaFuncSetAttribute(gemm_tf32<0>,
        cudaFuncAttributeMaxDynamicSharedMemorySize, GEMM_SMEM);
    cudaFuncSetAttribute(flash4,
        cudaFuncAttributeMaxDynamicSharedMemorySize, F3_SMEM);

    // 0) fused tf32 rounding pre-pass (RNA) for all GEMM operands
    round3_kernel<<<(N4TOT + 255)/256, 256>>>(x, xr, w_qkv, wqkvr, w_proj, wprojr);

    // 1) QKV GEMM + bias -> scatter into Q/K/V [b,h,s,d] (tf32-rounded)
    {
        dim3 grid(NQKV/128, MROWS/128);   // (24, 32)
        gemm_tf32<1><<<grid, 256, GEMM_SMEM>>>(xr, wqkvr, b_qkv, nullptr);
    }
    // 2) flash attention v4 -> g_attn [b,s,D] (tf32-rounded)
    {
        dim3 grid(SEQ/128, BATCH*HEADS);  // (16, 32)
        flash4<<<grid, 256, F3_SMEM>>>(attn_ptr);
    }
    // 3) output projection + bias -> d_out
    {
        dim3 grid(DIM/128, MROWS/128);    // (8, 32)
        gemm_tf32<0><<<grid, 256, GEMM_SMEM>>>(attn_ptr, wprojr, b_proj, out);
    }
}